// round 10
// baseline (speedup 1.0000x reference)
#include <cuda_runtime.h>
#include <cuda_bf16.h>

#define B_    32
#define H_    64
#define KVH_  8
#define D_    128
#define HID_  8192
#define CL_   1024
#define SP_   511
#define NTOT  10240

// ---------------- scratch ----------------
__device__ float    g_qkv[B_ * NTOT];       // fp32 qkv [b][n] (split-K accumulated)
__device__ unsigned g_xhi[B_ * 4096];       // x hi bf16x2 [b][k/2]
__device__ unsigned g_xlo[B_ * 4096];
__device__ unsigned g_ahi[B_ * 4096];       // attn out hi bf16x2 [b][k/2]
__device__ unsigned g_alo[B_ * 4096];
__device__ float    g_part[2048 * 8 * 132]; // attn partials

// gemm smem (48 KB): WHI[2]x8K, WLO[2]x8K, BHI[2]x4K, BLO[2]x4K
#define SMW_HI(buf) ((buf) * 8192)
#define SMW_LO(buf) (16384 + (buf) * 8192)
#define SMB_HI(buf) (32768 + (buf) * 4096)
#define SMB_LO(buf) (40960 + (buf) * 4096)
#define SM_TOT 49152

// ---------------- helpers ----------------
__device__ __forceinline__ void split2(float f0, float f1, unsigned& hi, unsigned& lo) {
    __nv_bfloat162 h = __floats2bfloat162_rn(f0, f1);
    unsigned hb = *reinterpret_cast<unsigned*>(&h);
    float h0 = __uint_as_float(hb << 16);
    float h1 = __uint_as_float(hb & 0xffff0000u);
    __nv_bfloat162 l = __floats2bfloat162_rn(f0 - h0, f1 - h1);
    hi = hb;
    lo = *reinterpret_cast<unsigned*>(&l);
}

__device__ __forceinline__ void ldsm4(unsigned& r0, unsigned& r1, unsigned& r2,
                                      unsigned& r3, unsigned addr) {
    asm volatile("ldmatrix.sync.aligned.m8n8.x4.shared.b16 {%0,%1,%2,%3}, [%4];"
                 : "=r"(r0), "=r"(r1), "=r"(r2), "=r"(r3) : "r"(addr));
}

__device__ __forceinline__ void mma16816(float* c, const unsigned* a,
                                         unsigned b0, unsigned b1) {
    asm volatile(
        "mma.sync.aligned.m16n8k16.row.col.f32.bf16.bf16.f32 "
        "{%0,%1,%2,%3}, {%4,%5,%6,%7}, {%8,%9}, {%0,%1,%2,%3};"
        : "+f"(c[0]), "+f"(c[1]), "+f"(c[2]), "+f"(c[3])
        : "r"(a[0]), "r"(a[1]), "r"(a[2]), "r"(a[3]), "r"(b0), "r"(b1));
}

// ---------------- fused zero + cvt ----------------
__global__ void prep_kernel(const float* __restrict__ x, float* __restrict__ out) {
    const int n1 = B_ * NTOT;           // g_qkv
    const int n2 = B_ * HID_;           // d_out
    const int n3 = B_ * HID_ / 2;       // x pairs
    int t = blockIdx.x * blockDim.x + threadIdx.x;
    if (t < n1) {
        g_qkv[t] = 0.0f;
    } else if (t < n1 + n2) {
        out[t - n1] = 0.0f;
    } else if (t < n1 + n2 + n3) {
        int i = t - n1 - n2;
        float f0 = x[2 * i], f1 = x[2 * i + 1];
        unsigned h, l;
        split2(f0, f1, h, l);
        g_xhi[i] = h;
        g_xlo[i] = l;
    }
}

// ---------------- HMMA GEMM (BM=64, Kchunk=64, 8 warps, split-K=8) ----------
// Lookahead-2 register pipeline: LDG(c+2) issued at iter c, stored at iter c+1.
__global__ __launch_bounds__(256, 3)
void gemm_mma(int bsel,
              const float* __restrict__ W0, const float* __restrict__ W1,
              const float* __restrict__ W2,
              int nb1, int nb2,
              int csel, float* __restrict__ Cext, int ldc)
{
    extern __shared__ char smem[];
    unsigned sb = (unsigned)__cvta_generic_to_shared(smem);
    int tid = threadIdx.x, lane = tid & 31, wid = tid >> 5;

    int n0 = blockIdx.x * 64;
    const float* W; int wrow;
    if (n0 < nb1)      { W = W0; wrow = n0; }
    else if (n0 < nb2) { W = W1; wrow = n0 - nb1; }
    else               { W = W2; wrow = n0 - nb2; }

    const unsigned* __restrict__ Bh = bsel ? g_ahi : g_xhi;
    const unsigned* __restrict__ Bl = bsel ? g_alo : g_xlo;
    float* C = csel ? Cext : g_qkv;

    int kbase = blockIdx.y * (HID_ / 8);                // split-K=8
    const float* wbase = W + (size_t)wrow * HID_ + kbase;
    int kw0 = kbase >> 1;

    // warp tiling: 4 row-groups x 2 batch-halves
    int rg   = wid >> 1;
    int bh16 = wid & 1;

    // ldmatrix lane descriptors (row stride 128B = 8 segs)
    int arow = rg * 16 + (lane & 7) + ((lane >> 3) & 1) * 8;
    int acs  = (lane >> 4) & 1;
    int arm  = arow & 7;
    int brow = bh16 * 16 + (lane & 7) + ((lane >> 4) & 1) * 8;
    int bcs  = (lane >> 3) & 1;
    int brm  = brow & 7;

    float4 wregA[4], wregB[4];
    uint4  bhA, blA, bhB, blB;

    float acc[2][4];
    #pragma unroll
    for (int i = 0; i < 2; ++i)
        #pragma unroll
        for (int j = 0; j < 4; ++j) acc[i][j] = 0.0f;

    #define LOADC(c, WR, BHR, BLR) do {                                          \
        _Pragma("unroll")                                                        \
        for (int i_ = 0; i_ < 4; ++i_) {                                         \
            int idx_ = tid + 256 * i_;                                           \
            int row_ = idx_ >> 4, kq_ = idx_ & 15;                               \
            WR[i_] = __ldcs((const float4*)(wbase + (c) * 64                     \
                            + (size_t)row_ * HID_ + kq_ * 4));                   \
        }                                                                        \
        {                                                                        \
            int n_ = tid >> 3, s_ = tid & 7;                                     \
            size_t off_ = (size_t)n_ * 4096 + kw0 + (c) * 32 + s_ * 4;           \
            BHR = *(const uint4*)(Bh + off_);                                    \
            BLR = *(const uint4*)(Bl + off_);                                    \
        }                                                                        \
    } while (0)

    #define STOREC(buf, WR, BHR, BLR) do {                                       \
        _Pragma("unroll")                                                        \
        for (int i_ = 0; i_ < 4; ++i_) {                                         \
            int idx_ = tid + 256 * i_;                                           \
            int row_ = idx_ >> 4, kq_ = idx_ & 15;                               \
            unsigned h0_, l0_, h1_, l1_;                                         \
            split2(WR[i_].x, WR[i_].y, h0_, l0_);                                \
            split2(WR[i_].z, WR[i_].w, h1_, l1_);                                \
            unsigned off_ = (unsigned)(row_ * 128)                               \
                          + ((((unsigned)kq_ >> 1) ^ (unsigned)(row_ & 7)) << 4) \
                          + (((unsigned)kq_ & 1u) << 3);                         \
            *(uint2*)(smem + SMW_HI(buf) + off_) = make_uint2(h0_, h1_);         \
            *(uint2*)(smem + SMW_LO(buf) + off_) = make_uint2(l0_, l1_);         \
        }                                                                        \
        {                                                                        \
            int n_ = tid >> 3, s_ = tid & 7;                                     \
            unsigned off_ = (unsigned)(n_ * 128)                                 \
                          + (((unsigned)s_ ^ (unsigned)(n_ & 7)) << 4);          \
            *(uint4*)(smem + SMB_HI(buf) + off_) = BHR;                          \
            *(uint4*)(smem + SMB_LO(buf) + off_) = BLR;                          \
        }                                                                        \
    } while (0)

    #define COMPUTE(buf) do {                                                    \
        unsigned wh0 = sb + SMW_HI(buf), wl0 = sb + SMW_LO(buf);                 \
        unsigned bb0 = sb + SMB_HI(buf), bl0 = sb + SMB_LO(buf);                 \
        _Pragma("unroll")                                                        \
        for (int s = 0; s < 4; ++s) {                                            \
            unsigned aoff = (unsigned)(arow * 128)                               \
                          + (((unsigned)(2 * s + acs) ^ (unsigned)arm) << 4);    \
            unsigned ah[4], al[4];                                               \
            ldsm4(ah[0], ah[1], ah[2], ah[3], wh0 + aoff);                       \
            ldsm4(al[0], al[1], al[2], al[3], wl0 + aoff);                       \
            unsigned boff = (unsigned)(brow * 128)                               \
                          + (((unsigned)(2 * s + bcs) ^ (unsigned)brm) << 4);    \
            unsigned bh[4], bl[4];                                               \
            ldsm4(bh[0], bh[1], bh[2], bh[3], bb0 + boff);                       \
            ldsm4(bl[0], bl[1], bl[2], bl[3], bl0 + boff);                       \
            mma16816(acc[0], ah, bh[0], bh[1]);                                  \
            mma16816(acc[1], ah, bh[2], bh[3]);                                  \
            mma16816(acc[0], al, bh[0], bh[1]);                                  \
            mma16816(acc[1], al, bh[2], bh[3]);                                  \
            mma16816(acc[0], ah, bl[0], bl[1]);                                  \
            mma16816(acc[1], ah, bl[2], bl[3]);                                  \
        }                                                                        \
    } while (0)

    const int NCH = (HID_ / 8) / 64;    // 16 chunks

    // prologue: chunks 0 (A) and 1 (B); stage chunk 0
    LOADC(0, wregA, bhA, blA);
    LOADC(1, wregB, bhB, blB);
    STOREC(0, wregA, bhA, blA);
    __syncthreads();

    for (int c = 0; c < NCH; c += 2) {
        // even chunk c: buf0
        if (c + 2 < NCH) LOADC(c + 2, wregA, bhA, blA);
        COMPUTE(0);
        STOREC(1, wregB, bhB, blB);          // chunk c+1 (always exists, NCH even)
        __syncthreads();

        // odd chunk c+1: buf1
        if (c + 3 < NCH) LOADC(c + 3, wregB, bhB, blB);
        COMPUTE(1);
        if (c + 2 < NCH) STOREC(0, wregA, bhA, blA);   // chunk c+2
        __syncthreads();
    }

    // epilogue: split-K accumulate
    int g = lane >> 2, t4 = lane & 3;
    int m = n0 + rg * 16 + g;
    #pragma unroll
    for (int nt = 0; nt < 2; ++nt) {
        int col = bh16 * 16 + nt * 8 + 2 * t4;
        atomicAdd(&C[(size_t)col * ldc + m],           acc[nt][0]);
        atomicAdd(&C[(size_t)(col + 1) * ldc + m],     acc[nt][1]);
        atomicAdd(&C[(size_t)col * ldc + m + 8],       acc[nt][2]);
        atomicAdd(&C[(size_t)(col + 1) * ldc + m + 8], acc[nt][3]);
    }
    #undef LOADC
    #undef STOREC
    #undef COMPUTE
}

// ---------------- RoPE (pairwise) ----------------
__global__ void rope_kernel(const float* __restrict__ rm) {
    int t = blockIdx.x * blockDim.x + threadIdx.x;   // 147456
    int p  = t & 63;
    int hr = t >> 6;
    int b  = hr / (H_ + KVH_);
    int hh = hr % (H_ + KVH_);
    float* ptr;
    if (hh < H_) ptr = g_qkv + (size_t)b * NTOT + hh * D_;
    else         ptr = g_qkv + (size_t)b * NTOT + HID_ + (hh - H_) * D_;
    float c = rm[(2 * p) * D_ + 2 * p];
    float s = rm[(2 * p + 1) * D_ + 2 * p];
    float e = ptr[2 * p], o = ptr[2 * p + 1];
    ptr[2 * p]     = fmaf(e, c,  o * s);
    ptr[2 * p + 1] = fmaf(o, c, -e * s);
}

// ---------------- attention split (8 splits x 64 pos, shuffle-free) ---------
__global__ __launch_bounds__(256)
void attn_split(const float* __restrict__ cache_k,
                const float* __restrict__ cache_v)
{
    int bidx  = blockIdx.x;            // ((b*8+kv)*8 + split), 0..2047
    int split = bidx & 7;
    int bk    = bidx >> 3;
    int b  = bk >> 3;
    int kv = bk & 7;
    int p0 = split * 64;

    int tid  = threadIdx.x;
    int r    = tid >> 5;
    int lane = tid & 31;

    __shared__ float sQ[8][128];
    __shared__ float sK[64][128];
    __shared__ float sP[8][64];

    const float scale = 0.0883883476483184405501055452631f;

    const float* kb   = cache_k + ((size_t)(b * KVH_ + kv)) * CL_ * D_;
    const float* vb   = cache_v + ((size_t)(b * KVH_ + kv)) * CL_ * D_;
    const float* knew = g_qkv + (size_t)b * NTOT + HID_ + kv * D_;
    const float* vnew = g_qkv + (size_t)b * NTOT + HID_ + KVH_ * D_ + kv * D_;

    {
        int h = tid >> 5, part = tid & 31;
        float4 q = *(const float4*)(g_qkv + (size_t)b * NTOT + (kv * 8 + h) * D_ + part * 4);
        q.x *= scale; q.y *= scale; q.z *= scale; q.w *= scale;
        *(float4*)&sQ[h][part * 4] = q;
    }
    #pragma unroll
    for (int i = 0; i < 8; ++i) {
        int v = tid + 256 * i;
        int j = v >> 5, dq = v & 31;
        int s = p0 + j;
        float4 kd = (s == SP_) ? *(const float4*)(knew + dq * 4)
                               : __ldcs((const float4*)(kb + (size_t)s * D_ + dq * 4));
        *(float4*)&sK[j][(dq ^ (j & 31)) << 2] = kd;
    }
    __syncthreads();

    float s1 = 0.0f, s2 = 0.0f;
    #pragma unroll
    for (int c = 0; c < 32; ++c) {
        float4 qc = *(const float4*)&sQ[r][c * 4];
        float4 k1 = *(const float4*)&sK[lane][(c ^ lane) << 2];
        float4 k2 = *(const float4*)&sK[lane + 32][(c ^ lane) << 2];
        s1 = fmaf(qc.x, k1.x, fmaf(qc.y, k1.y, fmaf(qc.z, k1.z, fmaf(qc.w, k1.w, s1))));
        s2 = fmaf(qc.x, k2.x, fmaf(qc.y, k2.y, fmaf(qc.z, k2.z, fmaf(qc.w, k2.w, s2))));
    }

    float mx = fmaxf(s1, s2);
    #pragma unroll
    for (int o = 16; o; o >>= 1) mx = fmaxf(mx, __shfl_xor_sync(0xffffffffu, mx, o));
    float e1 = __expf(s1 - mx), e2 = __expf(s2 - mx);
    float sum = e1 + e2;
    #pragma unroll
    for (int o = 16; o; o >>= 1) sum += __shfl_xor_sync(0xffffffffu, sum, o);
    sP[r][lane]      = e1;
    sP[r][lane + 32] = e2;

    __syncthreads();
    #pragma unroll
    for (int i = 0; i < 8; ++i) {
        int v = tid + 256 * i;
        int j = v >> 5, dq = v & 31;
        int s = p0 + j;
        float4 vd = (s == SP_) ? *(const float4*)(vnew + dq * 4)
                               : __ldcs((const float4*)(vb + (size_t)s * D_ + dq * 4));
        *(float4*)&sK[j][(dq ^ (j & 31)) << 2] = vd;
    }
    __syncthreads();

    float4 acc = make_float4(0.f, 0.f, 0.f, 0.f);
    #pragma unroll 8
    for (int j = 0; j < 64; ++j) {
        float pw = sP[r][j];
        float4 v4 = *(const float4*)&sK[j][(lane ^ (j & 31)) << 2];
        acc.x = fmaf(pw, v4.x, acc.x);
        acc.y = fmaf(pw, v4.y, acc.y);
        acc.z = fmaf(pw, v4.z, acc.z);
        acc.w = fmaf(pw, v4.w, acc.w);
    }

    float* p = g_part + ((size_t)bidx * 8 + r) * 132;
    *(float4*)(p + lane * 4) = acc;
    if (lane == 0) { p[128] = mx; p[129] = sum; }
}

// ---------------- combine partials -> bf16 hi/lo attn output ----------------
__global__ __launch_bounds__(256)
void combine_attn() {
    int w = blockIdx.x * 8 + (threadIdx.x >> 5);   // 0..2047 = (b,h)
    int lane = threadIdx.x & 31;
    int b = w >> 6, h = w & 63;
    int kv = h >> 3, r = h & 7;

    float m[8], s[8];
    float4 a[8];
    #pragma unroll
    for (int i = 0; i < 8; ++i) {
        const float* p = g_part + ((size_t)((b * 8 + kv) * 8 + i) * 8 + r) * 132;
        a[i] = *(const float4*)(p + lane * 4);
        m[i] = p[128];
        s[i] = p[129];
    }
    float M = m[0];
    #pragma unroll
    for (int i = 1; i < 8; ++i) M = fmaxf(M, m[i]);
    float wsum = 0.0f;
    float4 o = make_float4(0.f, 0.f, 0.f, 0.f);
    #pragma unroll
    for (int i = 0; i < 8; ++i) {
        float wi = __expf(m[i] - M);
        wsum += wi * s[i];
        o.x = fmaf(wi, a[i].x, o.x);
        o.y = fmaf(wi, a[i].y, o.y);
        o.z = fmaf(wi, a[i].z, o.z);
        o.w = fmaf(wi, a[i].w, o.w);
    }
    float inv = 1.0f / wsum;
    o.x *= inv; o.y *= inv; o.z *= inv; o.w *= inv;

    unsigned h0, l0, h1, l1;
    split2(o.x, o.y, h0, l0);
    split2(o.z, o.w, h1, l1);
    size_t wb = (size_t)b * 4096 + h * 64 + lane * 2;
    g_ahi[wb]     = h0;
    g_ahi[wb + 1] = h1;
    g_alo[wb]     = l0;
    g_alo[wb + 1] = l1;
}

// ---------------- launcher ----------------
extern "C" void kernel_launch(void* const* d_in, const int* in_sizes, int n_in,
                              void* d_out, int out_size) {
    const float* x  = (const float*)d_in[0];
    const float* wq = (const float*)d_in[1];
    const float* wk = (const float*)d_in[2];
    const float* wv = (const float*)d_in[3];
    const float* wo = (const float*)d_in[4];
    const float* ck = (const float*)d_in[5];
    const float* cv = (const float*)d_in[6];
    const float* rm = (const float*)d_in[7];
    float* out = (float*)d_out;

    cudaFuncSetAttribute(gemm_mma, cudaFuncAttributeMaxDynamicSharedMemorySize, SM_TOT);

    // 1. fused: zero g_qkv + d_out, split x into bf16 hi/lo
    prep_kernel<<<2816, 256>>>(x, out);

    // 2. fused QKV projection: 160 row-tiles x split-K 8
    gemm_mma<<<dim3(160, 8), 256, SM_TOT>>>(0, wq, wk, wv, 8192, 9216,
                                            0, nullptr, NTOT);

    // 3. RoPE on q and k
    rope_kernel<<<576, 256>>>(rm);

    // 4. attention: 8-way flash-decode split + combine
    attn_split<<<2048, 256>>>(ck, cv);
    combine_attn<<<256, 256>>>();

    // 5. output projection: 128 row-tiles x split-K 8 into d_out
    gemm_mma<<<dim3(128, 8), 256, SM_TOT>>>(1, wo, wo, wo, 1 << 30, 1 << 30,
                                            1, out, HID_);
}

// round 11
// speedup vs baseline: 1.0967x; 1.0967x over previous
#include <cuda_runtime.h>
#include <cuda_bf16.h>

#define B_    32
#define H_    64
#define KVH_  8
#define D_    128
#define HID_  8192
#define CL_   1024
#define SP_   511
#define NTOT  10240

// ---------------- scratch ----------------
__device__ float    g_qkv[B_ * NTOT];       // fp32 qkv [b][n] (split-K accumulated)
__device__ unsigned g_xhi[B_ * 4096];       // x hi bf16x2 [b][k/2]
__device__ unsigned g_xlo[B_ * 4096];
__device__ unsigned g_ahi[B_ * 4096];       // attn out hi bf16x2 [b][k/2]
__device__ unsigned g_alo[B_ * 4096];
__device__ float    g_part[2048 * 8 * 132]; // attn partials [(b,kv,split)][head][128 acc + m + s]

// gemm smem (48 KB): WHI[2]x8K, WLO[2]x8K, BHI[2]x4K, BLO[2]x4K
#define SMW_HI(buf) ((buf) * 8192)
#define SMW_LO(buf) (16384 + (buf) * 8192)
#define SMB_HI(buf) (32768 + (buf) * 4096)
#define SMB_LO(buf) (40960 + (buf) * 4096)
#define SM_TOT 49152

// ---------------- helpers ----------------
__device__ __forceinline__ void split2(float f0, float f1, unsigned& hi, unsigned& lo) {
    __nv_bfloat162 h = __floats2bfloat162_rn(f0, f1);
    unsigned hb = *reinterpret_cast<unsigned*>(&h);
    float h0 = __uint_as_float(hb << 16);
    float h1 = __uint_as_float(hb & 0xffff0000u);
    __nv_bfloat162 l = __floats2bfloat162_rn(f0 - h0, f1 - h1);
    hi = hb;
    lo = *reinterpret_cast<unsigned*>(&l);
}

__device__ __forceinline__ void ldsm4(unsigned& r0, unsigned& r1, unsigned& r2,
                                      unsigned& r3, unsigned addr) {
    asm volatile("ldmatrix.sync.aligned.m8n8.x4.shared.b16 {%0,%1,%2,%3}, [%4];"
                 : "=r"(r0), "=r"(r1), "=r"(r2), "=r"(r3) : "r"(addr));
}

__device__ __forceinline__ void mma16816(float* c, const unsigned* a,
                                         unsigned b0, unsigned b1) {
    asm volatile(
        "mma.sync.aligned.m16n8k16.row.col.f32.bf16.bf16.f32 "
        "{%0,%1,%2,%3}, {%4,%5,%6,%7}, {%8,%9}, {%0,%1,%2,%3};"
        : "+f"(c[0]), "+f"(c[1]), "+f"(c[2]), "+f"(c[3])
        : "r"(a[0]), "r"(a[1]), "r"(a[2]), "r"(a[3]), "r"(b0), "r"(b1));
}

// ---------------- fused zero + cvt ----------------
__global__ void prep_kernel(const float* __restrict__ x, float* __restrict__ out) {
    const int n1 = B_ * NTOT;
    const int n2 = B_ * HID_;
    const int n3 = B_ * HID_ / 2;
    int t = blockIdx.x * blockDim.x + threadIdx.x;
    if (t < n1) {
        g_qkv[t] = 0.0f;
    } else if (t < n1 + n2) {
        out[t - n1] = 0.0f;
    } else if (t < n1 + n2 + n3) {
        int i = t - n1 - n2;
        float f0 = x[2 * i], f1 = x[2 * i + 1];
        unsigned h, l;
        split2(f0, f1, h, l);
        g_xhi[i] = h;
        g_xlo[i] = l;
    }
}

// ---------------- HMMA GEMM (exact R9 config: Kchunk=64, split-K=4, occ 4) --
__global__ __launch_bounds__(256, 4)
void gemm_mma(int bsel,
              const float* __restrict__ W0, const float* __restrict__ W1,
              const float* __restrict__ W2,
              int nb1, int nb2,
              int csel, float* __restrict__ Cext, int ldc)
{
    extern __shared__ char smem[];
    unsigned sb = (unsigned)__cvta_generic_to_shared(smem);
    int tid = threadIdx.x, lane = tid & 31, wid = tid >> 5;

    int n0 = blockIdx.x * 64;
    const float* W; int wrow;
    if (n0 < nb1)      { W = W0; wrow = n0; }
    else if (n0 < nb2) { W = W1; wrow = n0 - nb1; }
    else               { W = W2; wrow = n0 - nb2; }

    const unsigned* __restrict__ Bh = bsel ? g_ahi : g_xhi;
    const unsigned* __restrict__ Bl = bsel ? g_alo : g_xlo;
    float* C = csel ? Cext : g_qkv;

    int kbase = blockIdx.y * (HID_ / 4);                // split-K=4
    const float* wbase = W + (size_t)wrow * HID_ + kbase;
    int kw0 = kbase >> 1;

    int rg   = wid >> 1;
    int bh16 = wid & 1;

    int arow = rg * 16 + (lane & 7) + ((lane >> 3) & 1) * 8;
    int acs  = (lane >> 4) & 1;
    int arm  = arow & 7;
    int brow = bh16 * 16 + (lane & 7) + ((lane >> 4) & 1) * 8;
    int bcs  = (lane >> 3) & 1;
    int brm  = brow & 7;

    float4 wreg[4];
    uint4  bhreg, blreg;

    float acc[2][4];
    #pragma unroll
    for (int i = 0; i < 2; ++i)
        #pragma unroll
        for (int j = 0; j < 4; ++j) acc[i][j] = 0.0f;

    #define LOADC(c) do {                                                        \
        _Pragma("unroll")                                                        \
        for (int i_ = 0; i_ < 4; ++i_) {                                         \
            int idx_ = tid + 256 * i_;                                           \
            int row_ = idx_ >> 4, kq_ = idx_ & 15;                               \
            wreg[i_] = __ldcs((const float4*)(wbase + (c) * 64                   \
                              + (size_t)row_ * HID_ + kq_ * 4));                 \
        }                                                                        \
        {                                                                        \
            int n_ = tid >> 3, s_ = tid & 7;                                     \
            size_t off_ = (size_t)n_ * 4096 + kw0 + (c) * 32 + s_ * 4;           \
            bhreg = *(const uint4*)(Bh + off_);                                  \
            blreg = *(const uint4*)(Bl + off_);                                  \
        }                                                                        \
    } while (0)

    #define STOREC(buf) do {                                                     \
        _Pragma("unroll")                                                        \
        for (int i_ = 0; i_ < 4; ++i_) {                                         \
            int idx_ = tid + 256 * i_;                                           \
            int row_ = idx_ >> 4, kq_ = idx_ & 15;                               \
            unsigned h0_, l0_, h1_, l1_;                                         \
            split2(wreg[i_].x, wreg[i_].y, h0_, l0_);                            \
            split2(wreg[i_].z, wreg[i_].w, h1_, l1_);                            \
            unsigned off_ = (unsigned)(row_ * 128)                               \
                          + ((((unsigned)kq_ >> 1) ^ (unsigned)(row_ & 7)) << 4) \
                          + (((unsigned)kq_ & 1u) << 3);                         \
            *(uint2*)(smem + SMW_HI(buf) + off_) = make_uint2(h0_, h1_);         \
            *(uint2*)(smem + SMW_LO(buf) + off_) = make_uint2(l0_, l1_);         \
        }                                                                        \
        {                                                                        \
            int n_ = tid >> 3, s_ = tid & 7;                                     \
            unsigned off_ = (unsigned)(n_ * 128)                                 \
                          + (((unsigned)s_ ^ (unsigned)(n_ & 7)) << 4);          \
            *(uint4*)(smem + SMB_HI(buf) + off_) = bhreg;                        \
            *(uint4*)(smem + SMB_LO(buf) + off_) = blreg;                        \
        }                                                                        \
    } while (0)

    LOADC(0);
    STOREC(0);
    __syncthreads();

    const int NCH = (HID_ / 4) / 64;    // 32 chunks
    for (int c = 0; c < NCH; ++c) {
        int buf = c & 1;
        if (c + 1 < NCH) LOADC(c + 1);

        unsigned wh0 = sb + SMW_HI(buf), wl0 = sb + SMW_LO(buf);
        unsigned bb0 = sb + SMB_HI(buf), bl0 = sb + SMB_LO(buf);
        #pragma unroll
        for (int s = 0; s < 4; ++s) {
            unsigned aoff = (unsigned)(arow * 128)
                          + (((unsigned)(2 * s + acs) ^ (unsigned)arm) << 4);
            unsigned ah[4], al[4];
            ldsm4(ah[0], ah[1], ah[2], ah[3], wh0 + aoff);
            ldsm4(al[0], al[1], al[2], al[3], wl0 + aoff);
            unsigned boff = (unsigned)(brow * 128)
                          + (((unsigned)(2 * s + bcs) ^ (unsigned)brm) << 4);
            unsigned bh[4], bl[4];
            ldsm4(bh[0], bh[1], bh[2], bh[3], bb0 + boff);
            ldsm4(bl[0], bl[1], bl[2], bl[3], bl0 + boff);

            mma16816(acc[0], ah, bh[0], bh[1]);
            mma16816(acc[1], ah, bh[2], bh[3]);
            mma16816(acc[0], al, bh[0], bh[1]);
            mma16816(acc[1], al, bh[2], bh[3]);
            mma16816(acc[0], ah, bl[0], bl[1]);
            mma16816(acc[1], ah, bl[2], bl[3]);
        }

        if (c + 1 < NCH) STOREC((c + 1) & 1);
        __syncthreads();
    }

    int g = lane >> 2, t4 = lane & 3;
    int m = n0 + rg * 16 + g;
    #pragma unroll
    for (int nt = 0; nt < 2; ++nt) {
        int col = bh16 * 16 + nt * 8 + 2 * t4;
        atomicAdd(&C[(size_t)col * ldc + m],           acc[nt][0]);
        atomicAdd(&C[(size_t)(col + 1) * ldc + m],     acc[nt][1]);
        atomicAdd(&C[(size_t)col * ldc + m + 8],       acc[nt][2]);
        atomicAdd(&C[(size_t)(col + 1) * ldc + m + 8], acc[nt][3]);
    }
    #undef LOADC
    #undef STOREC
}

// ---------------- RoPE (pairwise) ----------------
__global__ void rope_kernel(const float* __restrict__ rm) {
    int t = blockIdx.x * blockDim.x + threadIdx.x;   // 147456
    int p  = t & 63;
    int hr = t >> 6;
    int b  = hr / (H_ + KVH_);
    int hh = hr % (H_ + KVH_);
    float* ptr;
    if (hh < H_) ptr = g_qkv + (size_t)b * NTOT + hh * D_;
    else         ptr = g_qkv + (size_t)b * NTOT + HID_ + (hh - H_) * D_;
    float c = rm[(2 * p) * D_ + 2 * p];
    float s = rm[(2 * p + 1) * D_ + 2 * p];
    float e = ptr[2 * p], o = ptr[2 * p + 1];
    ptr[2 * p]     = fmaf(e, c,  o * s);
    ptr[2 * p + 1] = fmaf(o, c, -e * s);
}

// ---------------- attention split: warp=position-group, K/V read once -------
// Block = (b, kv, split of 64 positions). Warp w owns positions w*8..w*8+7.
// Lane = (head h = lane>>2, dim-quad dq4 = lane&3, 32 dims each, rotated).
__global__ __launch_bounds__(256)
void attn_split(const float* __restrict__ cache_k,
                const float* __restrict__ cache_v)
{
    int bidx  = blockIdx.x;            // ((b*8+kv)*8 + split)
    int split = bidx & 7;
    int bk    = bidx >> 3;
    int b  = bk >> 3;
    int kv = bk & 7;
    int p0 = split * 64;

    int tid  = threadIdx.x;
    int w    = tid >> 5;
    int lane = tid & 31;
    int h    = lane >> 2;
    int dq4  = lane & 3;

    __shared__ float sK[64 * 128];     // 32 KB: K, then V, then partial buffer
    __shared__ float sS[64 * 9];       // scores/probs, pad 9 (coprime 32)

    const float scale = 0.0883883476483184405501055452631f;

    const float* kb   = cache_k + ((size_t)(b * KVH_ + kv)) * CL_ * D_;
    const float* vb   = cache_v + ((size_t)(b * KVH_ + kv)) * CL_ * D_;
    const float* knew = g_qkv + (size_t)b * NTOT + HID_ + kv * D_;
    const float* vnew = g_qkv + (size_t)b * NTOT + HID_ + KVH_ * D_ + kv * D_;

    // q into registers, rotated quad order, pre-scaled
    float4 qreg[8];
    {
        const float* qr = g_qkv + (size_t)b * NTOT + (kv * 8 + h) * D_ + dq4 * 32;
        #pragma unroll
        for (int i = 0; i < 8; ++i) {
            int rot = (i + 2 * dq4) & 7;
            float4 q = *(const float4*)(qr + rot * 4);
            q.x *= scale; q.y *= scale; q.z *= scale; q.w *= scale;
            qreg[i] = q;
        }
    }

    // stage K (straight layout; rows read warp-uniform later)
    #pragma unroll
    for (int i = 0; i < 8; ++i) {
        int v = tid + 256 * i;
        int j = v >> 5, dq = v & 31;
        int s = p0 + j;
        float4 kd = (s == SP_) ? *(const float4*)(knew + dq * 4)
                               : __ldcs((const float4*)(kb + (size_t)s * D_ + dq * 4));
        *(float4*)&sK[j * 128 + dq * 4] = kd;
    }
    __syncthreads();

    // phase 1: scores (each K row read by exactly one warp)
    #pragma unroll
    for (int p = 0; p < 8; ++p) {
        int j = w * 8 + p;
        float s = 0.0f;
        #pragma unroll
        for (int i = 0; i < 8; ++i) {
            int rot = (i + 2 * dq4) & 7;
            float4 k4 = *(const float4*)&sK[j * 128 + dq4 * 32 + rot * 4];
            s = fmaf(qreg[i].x, k4.x, fmaf(qreg[i].y, k4.y,
                fmaf(qreg[i].z, k4.z, fmaf(qreg[i].w, k4.w, s))));
        }
        s += __shfl_xor_sync(0xffffffffu, s, 1);
        s += __shfl_xor_sync(0xffffffffu, s, 2);
        if (dq4 == 0) sS[j * 9 + h] = s;
    }
    __syncthreads();

    // phase 2: softmax, warp w = head w
    {
        float s1 = sS[lane * 9 + w];
        float s2 = sS[(lane + 32) * 9 + w];
        float mx = fmaxf(s1, s2);
        #pragma unroll
        for (int o = 16; o; o >>= 1) mx = fmaxf(mx, __shfl_xor_sync(0xffffffffu, mx, o));
        float e1 = __expf(s1 - mx), e2 = __expf(s2 - mx);
        float sum = e1 + e2;
        #pragma unroll
        for (int o = 16; o; o >>= 1) sum += __shfl_xor_sync(0xffffffffu, sum, o);
        sS[lane * 9 + w]        = e1;
        sS[(lane + 32) * 9 + w] = e2;
        if (lane == 0) {
            float* pp = g_part + ((size_t)bidx * 8 + w) * 132;
            pp[128] = mx;
            pp[129] = sum;
        }
    }
    __syncthreads();

    // restage V over sK
    #pragma unroll
    for (int i = 0; i < 8; ++i) {
        int v = tid + 256 * i;
        int j = v >> 5, dq = v & 31;
        int s = p0 + j;
        float4 vd = (s == SP_) ? *(const float4*)(vnew + dq * 4)
                               : __ldcs((const float4*)(vb + (size_t)s * D_ + dq * 4));
        *(float4*)&sK[j * 128 + dq * 4] = vd;
    }
    __syncthreads();

    // phase 3: partial out per warp (acc[i] <-> dim quad (i+2*dq4)&7)
    float4 acc[8];
    #pragma unroll
    for (int i = 0; i < 8; ++i) acc[i] = make_float4(0.f, 0.f, 0.f, 0.f);
    #pragma unroll
    for (int p = 0; p < 8; ++p) {
        int j = w * 8 + p;
        float pw = sS[j * 9 + h];
        #pragma unroll
        for (int i = 0; i < 8; ++i) {
            int rot = (i + 2 * dq4) & 7;
            float4 v4 = *(const float4*)&sK[j * 128 + dq4 * 32 + rot * 4];
            acc[i].x = fmaf(pw, v4.x, acc[i].x);
            acc[i].y = fmaf(pw, v4.y, acc[i].y);
            acc[i].z = fmaf(pw, v4.z, acc[i].z);
            acc[i].w = fmaf(pw, v4.w, acc[i].w);
        }
    }
    __syncthreads();   // everyone done reading V

    // write partials (i-interleaved: conflict-free stores and reads)
    #pragma unroll
    for (int i = 0; i < 8; ++i)
        *(float4*)&sK[w * 1024 + i * 128 + lane * 4] = acc[i];
    __syncthreads();

    // reduce across 8 warps; thread t -> (ip = t>>5, lp = t&31)
    {
        int ip = tid >> 5, lp = tid & 31;
        float4 r = make_float4(0.f, 0.f, 0.f, 0.f);
        #pragma unroll
        for (int ww = 0; ww < 8; ++ww) {
            float4 v = *(const float4*)&sK[ww * 1024 + ip * 128 + lp * 4];
            r.x += v.x; r.y += v.y; r.z += v.z; r.w += v.w;
        }
        int hh = lp >> 2, dd4 = lp & 3;
        int rot = (ip + 2 * dd4) & 7;
        int dim = dd4 * 32 + rot * 4;
        float* pp = g_part + ((size_t)bidx * 8 + hh) * 132;
        *(float4*)(pp + dim) = r;
    }
}

// ---------------- combine partials -> bf16 hi/lo attn output ----------------
__global__ __launch_bounds__(256)
void combine_attn() {
    int w = blockIdx.x * 8 + (threadIdx.x >> 5);   // 0..2047 = (b,h)
    int lane = threadIdx.x & 31;
    int b = w >> 6, h = w & 63;
    int kv = h >> 3, r = h & 7;

    float m[8], s[8];
    float4 a[8];
    #pragma unroll
    for (int i = 0; i < 8; ++i) {
        const float* p = g_part + ((size_t)((b * 8 + kv) * 8 + i) * 8 + r) * 132;
        a[i] = *(const float4*)(p + lane * 4);
        m[i] = p[128];
        s[i] = p[129];
    }
    float M = m[0];
    #pragma unroll
    for (int i = 1; i < 8; ++i) M = fmaxf(M, m[i]);
    float wsum = 0.0f;
    float4 o = make_float4(0.f, 0.f, 0.f, 0.f);
    #pragma unroll
    for (int i = 0; i < 8; ++i) {
        float wi = __expf(m[i] - M);
        wsum += wi * s[i];
        o.x = fmaf(wi, a[i].x, o.x);
        o.y = fmaf(wi, a[i].y, o.y);
        o.z = fmaf(wi, a[i].z, o.z);
        o.w = fmaf(wi, a[i].w, o.w);
    }
    float inv = 1.0f / wsum;
    o.x *= inv; o.y *= inv; o.z *= inv; o.w *= inv;

    unsigned h0, l0, h1, l1;
    split2(o.x, o.y, h0, l0);
    split2(o.z, o.w, h1, l1);
    size_t wb = (size_t)b * 4096 + h * 64 + lane * 2;
    g_ahi[wb]     = h0;
    g_ahi[wb + 1] = h1;
    g_alo[wb]     = l0;
    g_alo[wb + 1] = l1;
}

// ---------------- launcher ----------------
extern "C" void kernel_launch(void* const* d_in, const int* in_sizes, int n_in,
                              void* d_out, int out_size) {
    const float* x  = (const float*)d_in[0];
    const float* wq = (const float*)d_in[1];
    const float* wk = (const float*)d_in[2];
    const float* wv = (const float*)d_in[3];
    const float* wo = (const float*)d_in[4];
    const float* ck = (const float*)d_in[5];
    const float* cv = (const float*)d_in[6];
    const float* rm = (const float*)d_in[7];
    float* out = (float*)d_out;

    cudaFuncSetAttribute(gemm_mma, cudaFuncAttributeMaxDynamicSharedMemorySize, SM_TOT);

    // 1. fused: zero g_qkv + d_out, split x into bf16 hi/lo
    prep_kernel<<<2816, 256>>>(x, out);

    // 2. fused QKV projection: 160 row-tiles x split-K 4 (R9 config)
    gemm_mma<<<dim3(160, 4), 256, SM_TOT>>>(0, wq, wk, wv, 8192, 9216,
                                            0, nullptr, NTOT);

    // 3. RoPE on q and k
    rope_kernel<<<576, 256>>>(rm);

    // 4. attention: 8-way flash-decode split + combine
    attn_split<<<2048, 256>>>(ck, cv);
    combine_attn<<<256, 256>>>();

    // 5. output projection: 128 row-tiles x split-K 4 into d_out
    gemm_mma<<<dim3(128, 4), 256, SM_TOT>>>(1, wo, wo, wo, 1 << 30, 1 << 30,
                                            1, out, HID_);
}